// round 14
// baseline (speedup 1.0000x reference)
#include <cuda_runtime.h>
#include <cuda_fp16.h>
#include <cstdint>

#define DI __device__ __forceinline__

static constexpr int B_ROWS = 8192;
static constexpr int DIM    = 1024;
static constexpr int NCOLS  = 16384;   // 2*B
static constexpr int NTILE  = 128;     // NCOLS / NT

// GEMM tiling: CTA 128x128, 8 warps (2Mx4N), warp tile 64x32
static constexpr int MT = 128;
static constexpr int NT = 128;
static constexpr int KC = 64;                  // fp16 elems per K chunk (128 B rows)
static constexpr int NCHUNK = DIM / KC;        // 16

static constexpr int TILE_BYTES  = 128 * 128;          // 16 KB (one tile-chunk image)
static constexpr int STAGE_BYTES = 2 * TILE_BYTES;     // 32 KB (A + B)
static constexpr int NSTAGE      = 3;
static constexpr int SMEM_BYTES  = NSTAGE * STAGE_BYTES;  // 96 KB -> 2 CTAs/SM

static constexpr size_t TCH_BYTES  = 16384;             // tile-chunk image bytes
static constexpr size_t TILE_STRIDE = (size_t)NCHUNK * TCH_BYTES;  // 256 KB per tile

// -------- scratch: repacked, pre-swizzled tile images --------
__device__ __half g_a[B_ROWS * DIM];              // [64 m-tiles][16 chunks][16KB]
__device__ __half g_b[(size_t)NCOLS * DIM];       // [128 n-tiles][16 chunks][16KB]
__device__ float  g_part[(size_t)B_ROWS * NTILE];
__device__ float  g_rowloss[B_ROWS];
__device__ int    g_done = 0;                      // last-block counter (self-resetting)

// -------- helpers --------
DI uint32_t smem_u32(const void* p) {
    uint32_t a;
    asm("{ .reg .u64 t; cvta.to.shared.u64 t, %1; cvt.u32.u64 %0, t; }" : "=r"(a) : "l"(p));
    return a;
}
DI uint32_t swz(uint32_t off) { return off ^ ((off >> 3) & 0x70); }

DI void bulk_g2s(uint32_t dst, const void* src, uint32_t bytes, uint32_t mbar) {
    asm volatile(
        "cp.async.bulk.shared::cluster.global.mbarrier::complete_tx::bytes [%0], [%1], %2, [%3];"
        :: "r"(dst), "l"(src), "r"(bytes), "r"(mbar) : "memory");
}

#define MBAR_INIT(addr, cnt) \
    asm volatile("mbarrier.init.shared.b64 [%0], %1;" :: "r"(addr), "r"(cnt) : "memory")
#define MBAR_EXPECT_TX(addr, tx) \
    asm volatile("mbarrier.arrive.expect_tx.shared.b64 _, [%0], %1;" :: "r"(addr), "r"(tx) : "memory")
#define MBAR_WAIT(addr, ph) do {                                                  \
    asm volatile("{ .reg .pred P; WL%=:"                                          \
        " mbarrier.try_wait.parity.acquire.cta.shared::cta.b64 P, [%0], %1, 0x989680;" \
        " @P bra.uni WD%=; bra.uni WL%=; WD%=: }"                                 \
        :: "r"(addr), "r"(ph) : "memory");                                        \
} while (0)

DI void ldsm4(uint32_t* r, uint32_t addr) {
    asm volatile("ldmatrix.sync.aligned.m8n8.x4.shared.b16 {%0,%1,%2,%3}, [%4];"
                 : "=r"(r[0]), "=r"(r[1]), "=r"(r[2]), "=r"(r[3]) : "r"(addr));
}

DI void mma_f16(float* c, const uint32_t* a, const uint32_t* b) {
    asm volatile(
        "mma.sync.aligned.m16n8k16.row.col.f32.f16.f16.f32 "
        "{%0,%1,%2,%3}, {%4,%5,%6,%7}, {%8,%9}, {%0,%1,%2,%3};"
        : "+f"(c[0]), "+f"(c[1]), "+f"(c[2]), "+f"(c[3])
        : "r"(a[0]), "r"(a[1]), "r"(a[2]), "r"(a[3]), "r"(b[0]), "r"(b[1]));
}

// -------- block reduce (sum) for 256-thread blocks --------
DI float block_sum256(float v) {
    __shared__ float red[8];
    #pragma unroll
    for (int o = 16; o; o >>= 1) v += __shfl_xor_sync(0xFFFFFFFFu, v, o);
    if ((threadIdx.x & 31) == 0) red[threadIdx.x >> 5] = v;
    __syncthreads();
    if (threadIdx.x < 8) {
        v = red[threadIdx.x];
        #pragma unroll
        for (int o = 4; o; o >>= 1) v += __shfl_xor_sync(0xFFu, v, o);
        if (threadIdx.x == 0) red[0] = v;
    }
    __syncthreads();
    return red[0];
}

// ============ Kernel 1: L2-normalize rows -> fp16, repacked swizzled images ============
__global__ void __launch_bounds__(256) norm_split_kernel(
    const float* __restrict__ p, const float* __restrict__ e, const float* __restrict__ c)
{
    int row = blockIdx.x;
    const float* src;
    char* arr;
    int prow;
    bool is_a = (row < B_ROWS);
    if (is_a) {
        src = p + (size_t)row * DIM;
        arr = (char*)g_a; prow = row;
    } else if (row < 2 * B_ROWS) {
        src = e + (size_t)(row - B_ROWS) * DIM;
        arr = (char*)g_b; prow = row - B_ROWS;
    } else {
        src = c + (size_t)(row - 2 * B_ROWS) * DIM;
        arr = (char*)g_b; prow = row - B_ROWS;   // contra after entail
    }
    int tile = prow >> 7, r = prow & 127;

    float4 x = reinterpret_cast<const float4*>(src)[threadIdx.x];
    float ss = x.x * x.x + x.y * x.y + x.z * x.z + x.w * x.w;
    float tot = block_sum256(ss);
    float scale = (is_a ? 20.0f : 1.0f) / fmaxf(sqrtf(tot), 1e-8f);

    __half2 h0 = __floats2half2_rn(x.x * scale, x.y * scale);
    __half2 h1 = __floats2half2_rn(x.z * scale, x.w * scale);

    int k = threadIdx.x * 4;
    int chunk = k >> 6;
    int kin = k & 63;
    int kc = kin >> 3;
    int sub = (kin & 7) * 2;
    char* dst = arr + (size_t)tile * TILE_STRIDE + (size_t)chunk * TCH_BYTES
                    + swz((uint32_t)(r * 128 + kc * 16)) + sub;
    *reinterpret_cast<__half2*>(dst + 0) = h0;
    *reinterpret_cast<__half2*>(dst + 4) = h1;
}

// ============ Kernel 2: fp16 HMMA GEMM (bulk loader) + fused partial LSE ============
// 256 threads, CTA tile 128x128, warp tile 64x32, warps 2(M)x4(N),
// 3-stage cp.async.bulk pipeline with tx mbarriers; block-wide syncthreads
// protects slot recycling (WAR); ISSUE happens before the full-wait. 2 CTAs/SM.
__global__ void __launch_bounds__(256, 2) gemm_kernel(float* __restrict__ out) {
    extern __shared__ char smem[];
    __shared__ uint64_t mbars[NSTAGE];
    uint32_t sb = smem_u32(smem);
    uint32_t mb0 = smem_u32(mbars);
    int tid = threadIdx.x, w = tid >> 5, lane = tid & 31;

    // supertile swizzle: groups of 8 M-tiles, sweep all 128 N-tiles per group
    int sid = blockIdx.x;
    int group  = sid >> 10;
    int within = sid & 1023;
    int mt = (group << 3) + (within & 7);
    int nt = within >> 3;
    int m0 = mt * MT, n0 = nt * NT;

    const char* a_src = (const char*)g_a + (size_t)mt * TILE_STRIDE;
    const char* b_src = (const char*)g_b + (size_t)nt * TILE_STRIDE;

    int wm = w & 1, wn = w >> 1;
    int warp_m = wm * 64, warp_n = wn * 32;

    float acc[4][4][4];
    #pragma unroll
    for (int a = 0; a < 4; a++)
        #pragma unroll
        for (int b = 0; b < 4; b++)
            #pragma unroll
            for (int k = 0; k < 4; k++) acc[a][b][k] = 0.0f;

    if (tid == 0) {
        #pragma unroll
        for (int s = 0; s < NSTAGE; s++) MBAR_INIT(mb0 + 8 * s, 1);
    }
    __syncthreads();

    #define ISSUE(chunk_) do {                                                   \
        int s_ = (chunk_) % NSTAGE;                                               \
        uint32_t bar_ = mb0 + 8 * s_;                                             \
        uint32_t stage_ = sb + s_ * STAGE_BYTES;                                  \
        MBAR_EXPECT_TX(bar_, STAGE_BYTES);                                        \
        bulk_g2s(stage_,              a_src + (size_t)(chunk_) * TCH_BYTES, TCH_BYTES, bar_); \
        bulk_g2s(stage_ + TILE_BYTES, b_src + (size_t)(chunk_) * TCH_BYTES, TCH_BYTES, bar_); \
    } while (0)

    if (tid == 0) { ISSUE(0); ISSUE(1); }

    int arow = warp_m + (lane & 15);
    int acol = (lane >> 4);
    int brow = (lane & 7) + ((lane >> 4) << 3);
    int bkh  = (lane >> 3) & 1;

    for (int chunk = 0; chunk < NCHUNK; ++chunk) {
        int slot = chunk % NSTAGE;
        int ph = (chunk / NSTAGE) & 1;
        __syncthreads();                      // all warps done with chunk-1 (incl. its slot reads)
        if (chunk + 2 < NCHUNK && tid == 0) ISSUE(chunk + 2);   // recycle chunk-1's slot (safe)
        MBAR_WAIT(mb0 + 8 * slot, ph);        // RAW: this chunk's data ready

        uint32_t stage = sb + slot * STAGE_BYTES;
        uint32_t A = stage, Bt = stage + TILE_BYTES;

        #pragma unroll
        for (int kk = 0; kk < 4; kk++) {
            uint32_t a_r[4][4];
            #pragma unroll
            for (int mb = 0; mb < 4; mb++) {
                uint32_t off = swz((uint32_t)(arow + mb * 16) * 128 + kk * 32 + acol * 16);
                ldsm4(a_r[mb], A + off);
            }
            uint32_t b_r[2][4];
            #pragma unroll
            for (int p = 0; p < 2; p++) {
                uint32_t off = swz((uint32_t)(warp_n + p * 16 + brow) * 128 + kk * 32 + bkh * 16);
                ldsm4(b_r[p], Bt + off);
            }
            #pragma unroll
            for (int mb = 0; mb < 4; mb++)
                #pragma unroll
                for (int p = 0; p < 2; p++)
                    #pragma unroll
                    for (int sub = 0; sub < 2; sub++)
                        mma_f16(acc[mb][p * 2 + sub], a_r[mb], &b_r[p][sub * 2]);
        }
    }

    // ---- epilogue 1: store sims (streaming scalar stores; base is 4B-aligned) ----
    float* o = out + 1;
    #pragma unroll
    for (int mb = 0; mb < 4; mb++) {
        int row = m0 + warp_m + mb * 16 + (lane >> 2);
        #pragma unroll
        for (int nb = 0; nb < 4; nb++) {
            int col = n0 + warp_n + nb * 8 + (lane & 3) * 2;
            float* p0 = o + (size_t)row * NCOLS + col;
            __stcs(p0 + 0, acc[mb][nb][0]);
            __stcs(p0 + 1, acc[mb][nb][1]);
            float* p1 = p0 + (size_t)8 * NCOLS;
            __stcs(p1 + 0, acc[mb][nb][2]);
            __stcs(p1 + 1, acc[mb][nb][3]);
        }
    }

    // ---- epilogue 2: fused partial logsumexp (sum of exp(sim - 20)) ----
    auto exp_poly = [](float v) -> float {       // e^v for v in [-45, ~1e-2]
        float t = v * 1.4426950408889634f;
        float fi = floorf(t);
        float f = t - fi;
        float p = 1.5403530393283441e-4f;
        p = p * f + 1.3333558146428443e-3f;
        p = p * f + 9.6181291076284771e-3f;
        p = p * f + 5.5504108664821580e-2f;
        p = p * f + 2.4022650695910071e-1f;
        p = p * f + 6.9314718055994531e-1f;
        p = p * f + 1.0f;
        return __int_as_float(((int)fi + 127) << 23) * p;
    };

    float s[8];
    #pragma unroll
    for (int i = 0; i < 8; i++) s[i] = 0.0f;
    #pragma unroll
    for (int mb = 0; mb < 4; mb++)
        #pragma unroll
        for (int nb = 0; nb < 4; nb++) {
            s[mb * 2 + 0] += exp_poly(acc[mb][nb][0] - 20.0f) + exp_poly(acc[mb][nb][1] - 20.0f);
            s[mb * 2 + 1] += exp_poly(acc[mb][nb][2] - 20.0f) + exp_poly(acc[mb][nb][3] - 20.0f);
        }
    #pragma unroll
    for (int i = 0; i < 8; i++) {
        s[i] += __shfl_xor_sync(0xFFFFFFFFu, s[i], 1);
        s[i] += __shfl_xor_sync(0xFFFFFFFFu, s[i], 2);
    }
    float* sred = reinterpret_cast<float*>(smem);   // [4 wn][128 rows]
    __syncthreads();     // all warps done with final chunk's slot reads
    if ((lane & 3) == 0) {
        #pragma unroll
        for (int mb = 0; mb < 4; mb++) {
            int rl = warp_m + mb * 16 + (lane >> 2);
            sred[wn * 128 + rl]     = s[mb * 2 + 0];
            sred[wn * 128 + rl + 8] = s[mb * 2 + 1];
        }
    }
    __syncthreads();
    if (tid < 128) {
        float t = (sred[tid] + sred[128 + tid]) + (sred[256 + tid] + sred[384 + tid]);
        g_part[(size_t)(m0 + tid) * NTILE + nt] = t;
    }
    #undef ISSUE
}

// ============ Kernel 3: row loss from partials + fused final mean ============
// 1024 blocks x 256 threads, 8 rows/block; the LAST block to finish also
// computes the mean (fixed reduction order by one block -> deterministic).
__global__ void __launch_bounds__(256) lse_kernel(const float* __restrict__ sims,
                                                  float* __restrict__ out) {
    int w = threadIdx.x >> 5, lane = threadIdx.x & 31;
    int row = blockIdx.x * 8 + w;
    const float* pr = g_part + (size_t)row * NTILE;
    float s = (pr[lane] + pr[lane + 32]) + (pr[lane + 64] + pr[lane + 96]);
    #pragma unroll
    for (int o = 16; o; o >>= 1) s += __shfl_xor_sync(0xFFFFFFFFu, s, o);
    if (lane == 0) {
        float diag = sims[(size_t)row * NCOLS + row];
        g_rowloss[row] = 20.0f + logf(s) - diag;
    }

    // last-block-done: final mean
    __shared__ int is_last;
    __threadfence();
    __syncthreads();
    if (threadIdx.x == 0) {
        int prev = atomicAdd(&g_done, 1);
        is_last = (prev == gridDim.x - 1);
    }
    __syncthreads();
    if (is_last) {
        __threadfence();
        float acc = 0.0f;
        for (int i = threadIdx.x; i < B_ROWS; i += 256) acc += g_rowloss[i];
        float tot = block_sum256(acc);
        if (threadIdx.x == 0) {
            out[0] = tot * (1.0f / (float)B_ROWS);
            g_done = 0;                         // self-reset for graph replays
        }
    }
}

// ============ launch ============
extern "C" void kernel_launch(void* const* d_in, const int* in_sizes, int n_in,
                              void* d_out, int out_size) {
    (void)in_sizes; (void)n_in; (void)out_size;
    const float* p = (const float*)d_in[0];
    const float* e = (const float*)d_in[1];
    const float* c = (const float*)d_in[2];
    float* out = (float*)d_out;

    norm_split_kernel<<<3 * B_ROWS, 256>>>(p, e, c);

    cudaFuncSetAttribute(gemm_kernel, cudaFuncAttributeMaxDynamicSharedMemorySize, SMEM_BYTES);
    gemm_kernel<<<(B_ROWS / MT) * (NCOLS / NT), 256, SMEM_BYTES>>>(out);

    lse_kernel<<<B_ROWS / 8, 256>>>(out + 1, out);
}

// round 15
// speedup vs baseline: 1.0021x; 1.0021x over previous
#include <cuda_runtime.h>
#include <cuda_fp16.h>
#include <cstdint>

#define DI __device__ __forceinline__

static constexpr int B_ROWS = 8192;
static constexpr int DIM    = 1024;
static constexpr int NCOLS  = 16384;   // 2*B
static constexpr int NTILE  = 128;     // NCOLS / NT

// GEMM tiling: CTA 128x128, 8 warps (2Mx4N), warp tile 64x32
static constexpr int MT = 128;
static constexpr int NT = 128;
static constexpr int KC = 64;                  // fp16 elems per K chunk (128 B rows)
static constexpr int NCHUNK = DIM / KC;        // 16

static constexpr int TILE_BYTES  = 128 * 128;          // 16 KB (one tile-chunk image)
static constexpr int STAGE_BYTES = 2 * TILE_BYTES;     // 32 KB (A + B)
static constexpr int NSTAGE      = 3;
static constexpr int SMEM_BYTES  = NSTAGE * STAGE_BYTES;  // 96 KB -> 2 CTAs/SM

static constexpr size_t TCH_BYTES  = 16384;             // tile-chunk image bytes
static constexpr size_t TILE_STRIDE = (size_t)NCHUNK * TCH_BYTES;  // 256 KB per tile

// -------- scratch: repacked, pre-swizzled tile images --------
__device__ __half g_a[B_ROWS * DIM];              // [64 m-tiles][16 chunks][16KB]
__device__ __half g_b[(size_t)NCOLS * DIM];       // [128 n-tiles][16 chunks][16KB]
__device__ float  g_part[(size_t)B_ROWS * NTILE];
__device__ float  g_rowloss[B_ROWS];
__device__ int    g_done = 0;                      // last-block counter (self-resetting)

// -------- helpers --------
DI uint32_t smem_u32(const void* p) {
    uint32_t a;
    asm("{ .reg .u64 t; cvta.to.shared.u64 t, %1; cvt.u32.u64 %0, t; }" : "=r"(a) : "l"(p));
    return a;
}
DI uint32_t swz(uint32_t off) { return off ^ ((off >> 3) & 0x70); }

DI void bulk_g2s(uint32_t dst, const void* src, uint32_t bytes, uint32_t mbar) {
    asm volatile(
        "cp.async.bulk.shared::cluster.global.mbarrier::complete_tx::bytes [%0], [%1], %2, [%3];"
        :: "r"(dst), "l"(src), "r"(bytes), "r"(mbar) : "memory");
}

#define MBAR_INIT(addr, cnt) \
    asm volatile("mbarrier.init.shared.b64 [%0], %1;" :: "r"(addr), "r"(cnt) : "memory")
#define MBAR_EXPECT_TX(addr, tx) \
    asm volatile("mbarrier.arrive.expect_tx.shared.b64 _, [%0], %1;" :: "r"(addr), "r"(tx) : "memory")
#define MBAR_WAIT(addr, ph) do {                                                  \
    asm volatile("{ .reg .pred P; WL%=:"                                          \
        " mbarrier.try_wait.parity.acquire.cta.shared::cta.b64 P, [%0], %1, 0x989680;" \
        " @P bra.uni WD%=; bra.uni WL%=; WD%=: }"                                 \
        :: "r"(addr), "r"(ph) : "memory");                                        \
} while (0)

DI void ldsm4(uint32_t* r, uint32_t addr) {
    asm volatile("ldmatrix.sync.aligned.m8n8.x4.shared.b16 {%0,%1,%2,%3}, [%4];"
                 : "=r"(r[0]), "=r"(r[1]), "=r"(r[2]), "=r"(r[3]) : "r"(addr));
}

DI void mma_f16(float* c, const uint32_t* a, const uint32_t* b) {
    asm volatile(
        "mma.sync.aligned.m16n8k16.row.col.f32.f16.f16.f32 "
        "{%0,%1,%2,%3}, {%4,%5,%6,%7}, {%8,%9}, {%0,%1,%2,%3};"
        : "+f"(c[0]), "+f"(c[1]), "+f"(c[2]), "+f"(c[3])
        : "r"(a[0]), "r"(a[1]), "r"(a[2]), "r"(a[3]), "r"(b[0]), "r"(b[1]));
}

// -------- block reduce (sum) for 256-thread blocks --------
DI float block_sum256(float v) {
    __shared__ float red[8];
    #pragma unroll
    for (int o = 16; o; o >>= 1) v += __shfl_xor_sync(0xFFFFFFFFu, v, o);
    if ((threadIdx.x & 31) == 0) red[threadIdx.x >> 5] = v;
    __syncthreads();
    if (threadIdx.x < 8) {
        v = red[threadIdx.x];
        #pragma unroll
        for (int o = 4; o; o >>= 1) v += __shfl_xor_sync(0xFFu, v, o);
        if (threadIdx.x == 0) red[0] = v;
    }
    __syncthreads();
    return red[0];
}

// ============ Kernel 1: L2-normalize rows -> fp16, repacked swizzled images ============
__global__ void __launch_bounds__(256) norm_split_kernel(
    const float* __restrict__ p, const float* __restrict__ e, const float* __restrict__ c)
{
    int row = blockIdx.x;
    const float* src;
    char* arr;
    int prow;
    bool is_a = (row < B_ROWS);
    if (is_a) {
        src = p + (size_t)row * DIM;
        arr = (char*)g_a; prow = row;
    } else if (row < 2 * B_ROWS) {
        src = e + (size_t)(row - B_ROWS) * DIM;
        arr = (char*)g_b; prow = row - B_ROWS;
    } else {
        src = c + (size_t)(row - 2 * B_ROWS) * DIM;
        arr = (char*)g_b; prow = row - B_ROWS;   // contra after entail
    }
    int tile = prow >> 7, r = prow & 127;

    float4 x = reinterpret_cast<const float4*>(src)[threadIdx.x];
    float ss = x.x * x.x + x.y * x.y + x.z * x.z + x.w * x.w;
    float tot = block_sum256(ss);
    float scale = (is_a ? 20.0f : 1.0f) / fmaxf(sqrtf(tot), 1e-8f);

    __half2 h0 = __floats2half2_rn(x.x * scale, x.y * scale);
    __half2 h1 = __floats2half2_rn(x.z * scale, x.w * scale);

    int k = threadIdx.x * 4;
    int chunk = k >> 6;
    int kin = k & 63;
    int kc = kin >> 3;
    int sub = (kin & 7) * 2;
    char* dst = arr + (size_t)tile * TILE_STRIDE + (size_t)chunk * TCH_BYTES
                    + swz((uint32_t)(r * 128 + kc * 16)) + sub;
    *reinterpret_cast<__half2*>(dst + 0) = h0;
    *reinterpret_cast<__half2*>(dst + 4) = h1;
}

// ============ Kernel 2: fp16 HMMA GEMM (bulk loader) + fused partial LSE ============
// 256 threads, CTA tile 128x128, warp tile 64x32, warps 2(M)x4(N),
// 3-stage cp.async.bulk pipeline with tx mbarriers; block-wide syncthreads
// protects slot recycling (WAR); ISSUE happens before the full-wait. 2 CTAs/SM.
__global__ void __launch_bounds__(256, 2) gemm_kernel(float* __restrict__ out) {
    extern __shared__ char smem[];
    __shared__ uint64_t mbars[NSTAGE];
    uint32_t sb = smem_u32(smem);
    uint32_t mb0 = smem_u32(mbars);
    int tid = threadIdx.x, w = tid >> 5, lane = tid & 31;

    // supertile swizzle: groups of 8 M-tiles, sweep all 128 N-tiles per group
    int sid = blockIdx.x;
    int group  = sid >> 10;
    int within = sid & 1023;
    int mt = (group << 3) + (within & 7);
    int nt = within >> 3;
    int m0 = mt * MT, n0 = nt * NT;

    const char* a_src = (const char*)g_a + (size_t)mt * TILE_STRIDE;
    const char* b_src = (const char*)g_b + (size_t)nt * TILE_STRIDE;

    int wm = w & 1, wn = w >> 1;
    int warp_m = wm * 64, warp_n = wn * 32;

    float acc[4][4][4];
    #pragma unroll
    for (int a = 0; a < 4; a++)
        #pragma unroll
        for (int b = 0; b < 4; b++)
            #pragma unroll
            for (int k = 0; k < 4; k++) acc[a][b][k] = 0.0f;

    if (tid == 0) {
        #pragma unroll
        for (int s = 0; s < NSTAGE; s++) MBAR_INIT(mb0 + 8 * s, 1);
    }
    __syncthreads();

    #define ISSUE(chunk_) do {                                                   \
        int s_ = (chunk_) % NSTAGE;                                               \
        uint32_t bar_ = mb0 + 8 * s_;                                             \
        uint32_t stage_ = sb + s_ * STAGE_BYTES;                                  \
        MBAR_EXPECT_TX(bar_, STAGE_BYTES);                                        \
        bulk_g2s(stage_,              a_src + (size_t)(chunk_) * TCH_BYTES, TCH_BYTES, bar_); \
        bulk_g2s(stage_ + TILE_BYTES, b_src + (size_t)(chunk_) * TCH_BYTES, TCH_BYTES, bar_); \
    } while (0)

    if (tid == 0) { ISSUE(0); ISSUE(1); }

    int arow = warp_m + (lane & 15);
    int acol = (lane >> 4);
    int brow = (lane & 7) + ((lane >> 4) << 3);
    int bkh  = (lane >> 3) & 1;

    for (int chunk = 0; chunk < NCHUNK; ++chunk) {
        int slot = chunk % NSTAGE;
        int ph = (chunk / NSTAGE) & 1;
        __syncthreads();                      // all warps done with chunk-1 (incl. its slot reads)
        if (chunk + 2 < NCHUNK && tid == 0) ISSUE(chunk + 2);   // recycle chunk-1's slot (safe)
        MBAR_WAIT(mb0 + 8 * slot, ph);        // RAW: this chunk's data ready

        uint32_t stage = sb + slot * STAGE_BYTES;
        uint32_t A = stage, Bt = stage + TILE_BYTES;

        #pragma unroll
        for (int kk = 0; kk < 4; kk++) {
            uint32_t a_r[4][4];
            #pragma unroll
            for (int mb = 0; mb < 4; mb++) {
                uint32_t off = swz((uint32_t)(arow + mb * 16) * 128 + kk * 32 + acol * 16);
                ldsm4(a_r[mb], A + off);
            }
            uint32_t b_r[2][4];
            #pragma unroll
            for (int p = 0; p < 2; p++) {
                uint32_t off = swz((uint32_t)(warp_n + p * 16 + brow) * 128 + kk * 32 + bkh * 16);
                ldsm4(b_r[p], Bt + off);
            }
            #pragma unroll
            for (int mb = 0; mb < 4; mb++)
                #pragma unroll
                for (int p = 0; p < 2; p++)
                    #pragma unroll
                    for (int sub = 0; sub < 2; sub++)
                        mma_f16(acc[mb][p * 2 + sub], a_r[mb], &b_r[p][sub * 2]);
        }
    }

    // ---- epilogue 1: store sims (streaming scalar stores; base is 4B-aligned) ----
    float* o = out + 1;
    #pragma unroll
    for (int mb = 0; mb < 4; mb++) {
        int row = m0 + warp_m + mb * 16 + (lane >> 2);
        #pragma unroll
        for (int nb = 0; nb < 4; nb++) {
            int col = n0 + warp_n + nb * 8 + (lane & 3) * 2;
            float* p0 = o + (size_t)row * NCOLS + col;
            __stcs(p0 + 0, acc[mb][nb][0]);
            __stcs(p0 + 1, acc[mb][nb][1]);
            float* p1 = p0 + (size_t)8 * NCOLS;
            __stcs(p1 + 0, acc[mb][nb][2]);
            __stcs(p1 + 1, acc[mb][nb][3]);
        }
    }

    // ---- epilogue 2: fused partial logsumexp (sum of exp(sim - 20)) ----
    auto exp_poly = [](float v) -> float {       // e^v for v in [-45, ~1e-2]
        float t = v * 1.4426950408889634f;
        float fi = floorf(t);
        float f = t - fi;
        float p = 1.5403530393283441e-4f;
        p = p * f + 1.3333558146428443e-3f;
        p = p * f + 9.6181291076284771e-3f;
        p = p * f + 5.5504108664821580e-2f;
        p = p * f + 2.4022650695910071e-1f;
        p = p * f + 6.9314718055994531e-1f;
        p = p * f + 1.0f;
        return __int_as_float(((int)fi + 127) << 23) * p;
    };

    float s[8];
    #pragma unroll
    for (int i = 0; i < 8; i++) s[i] = 0.0f;
    #pragma unroll
    for (int mb = 0; mb < 4; mb++)
        #pragma unroll
        for (int nb = 0; nb < 4; nb++) {
            s[mb * 2 + 0] += exp_poly(acc[mb][nb][0] - 20.0f) + exp_poly(acc[mb][nb][1] - 20.0f);
            s[mb * 2 + 1] += exp_poly(acc[mb][nb][2] - 20.0f) + exp_poly(acc[mb][nb][3] - 20.0f);
        }
    #pragma unroll
    for (int i = 0; i < 8; i++) {
        s[i] += __shfl_xor_sync(0xFFFFFFFFu, s[i], 1);
        s[i] += __shfl_xor_sync(0xFFFFFFFFu, s[i], 2);
    }
    float* sred = reinterpret_cast<float*>(smem);   // [4 wn][128 rows]
    __syncthreads();     // all warps done with final chunk's slot reads
    if ((lane & 3) == 0) {
        #pragma unroll
        for (int mb = 0; mb < 4; mb++) {
            int rl = warp_m + mb * 16 + (lane >> 2);
            sred[wn * 128 + rl]     = s[mb * 2 + 0];
            sred[wn * 128 + rl + 8] = s[mb * 2 + 1];
        }
    }
    __syncthreads();
    if (tid < 128) {
        float t = (sred[tid] + sred[128 + tid]) + (sred[256 + tid] + sred[384 + tid]);
        g_part[(size_t)(m0 + tid) * NTILE + nt] = t;
    }
    #undef ISSUE
}

// ============ Kernel 3: row loss from partials + fused final mean ============
// 1024 blocks x 256 threads, 8 rows/block; the LAST block to finish also
// computes the mean (fixed reduction order by one block -> deterministic).
__global__ void __launch_bounds__(256) lse_kernel(const float* __restrict__ sims,
                                                  float* __restrict__ out) {
    int w = threadIdx.x >> 5, lane = threadIdx.x & 31;
    int row = blockIdx.x * 8 + w;
    const float* pr = g_part + (size_t)row * NTILE;
    float s = (pr[lane] + pr[lane + 32]) + (pr[lane + 64] + pr[lane + 96]);
    #pragma unroll
    for (int o = 16; o; o >>= 1) s += __shfl_xor_sync(0xFFFFFFFFu, s, o);
    if (lane == 0) {
        float diag = sims[(size_t)row * NCOLS + row];
        g_rowloss[row] = 20.0f + logf(s) - diag;
    }

    // last-block-done: final mean
    __shared__ int is_last;
    __threadfence();
    __syncthreads();
    if (threadIdx.x == 0) {
        int prev = atomicAdd(&g_done, 1);
        is_last = (prev == gridDim.x - 1);
    }
    __syncthreads();
    if (is_last) {
        __threadfence();
        float acc = 0.0f;
        for (int i = threadIdx.x; i < B_ROWS; i += 256) acc += g_rowloss[i];
        float tot = block_sum256(acc);
        if (threadIdx.x == 0) {
            out[0] = tot * (1.0f / (float)B_ROWS);
            g_done = 0;                         // self-reset for graph replays
        }
    }
}

// ============ launch ============
extern "C" void kernel_launch(void* const* d_in, const int* in_sizes, int n_in,
                              void* d_out, int out_size) {
    (void)in_sizes; (void)n_in; (void)out_size;
    const float* p = (const float*)d_in[0];
    const float* e = (const float*)d_in[1];
    const float* c = (const float*)d_in[2];
    float* out = (float*)d_out;

    norm_split_kernel<<<3 * B_ROWS, 256>>>(p, e, c);

    cudaFuncSetAttribute(gemm_kernel, cudaFuncAttributeMaxDynamicSharedMemorySize, SMEM_BYTES);
    gemm_kernel<<<(B_ROWS / MT) * (NCOLS / NT), 256, SMEM_BYTES>>>(out);

    lse_kernel<<<B_ROWS / 8, 256>>>(out + 1, out);
}

// round 17
// speedup vs baseline: 1.0109x; 1.0089x over previous
#include <cuda_runtime.h>
#include <cuda_fp16.h>
#include <cstdint>

#define DI __device__ __forceinline__

static constexpr int B_ROWS = 8192;
static constexpr int DIM    = 1024;
static constexpr int NCOLS  = 16384;   // 2*B
static constexpr int NTILE  = 128;     // NCOLS / NT

// GEMM tiling: CTA 128x128, 8 warps (2Mx4N), warp tile 64x32
static constexpr int MT = 128;
static constexpr int NT = 128;
static constexpr int KC = 64;                  // fp16 elems per K chunk (128 B rows)
static constexpr int NCHUNK = DIM / KC;        // 16

static constexpr int TILE_BYTES  = 128 * 128;          // 16 KB (one tile-chunk image)
static constexpr int STAGE_BYTES = 2 * TILE_BYTES;     // 32 KB (A + B)
static constexpr int NSTAGE      = 3;
static constexpr int SMEM_BYTES  = NSTAGE * STAGE_BYTES;  // 96 KB -> 2 CTAs/SM

static constexpr size_t TCH_BYTES  = 16384;             // tile-chunk image bytes
static constexpr size_t TILE_STRIDE = (size_t)NCHUNK * TCH_BYTES;  // 256 KB per tile

// -------- scratch: repacked, pre-swizzled tile images --------
__device__ __half g_a[B_ROWS * DIM];              // [64 m-tiles][16 chunks][16KB]
__device__ __half g_b[(size_t)NCOLS * DIM];       // [128 n-tiles][16 chunks][16KB]
__device__ float  g_part[(size_t)B_ROWS * NTILE];
__device__ float  g_rowloss[B_ROWS];
__device__ int    g_done = 0;                      // last-block counter (self-resetting)

// -------- helpers --------
DI uint32_t smem_u32(const void* p) {
    uint32_t a;
    asm("{ .reg .u64 t; cvta.to.shared.u64 t, %1; cvt.u32.u64 %0, t; }" : "=r"(a) : "l"(p));
    return a;
}
DI uint32_t swz(uint32_t off) { return off ^ ((off >> 3) & 0x70); }
DI uint32_t h2u(__half2 h) { return *reinterpret_cast<uint32_t*>(&h); }

DI void bulk_g2s(uint32_t dst, const void* src, uint32_t bytes, uint32_t mbar) {
    asm volatile(
        "cp.async.bulk.shared::cluster.global.mbarrier::complete_tx::bytes [%0], [%1], %2, [%3];"
        :: "r"(dst), "l"(src), "r"(bytes), "r"(mbar) : "memory");
}

#define MBAR_INIT(addr, cnt) \
    asm volatile("mbarrier.init.shared.b64 [%0], %1;" :: "r"(addr), "r"(cnt) : "memory")
#define MBAR_EXPECT_TX(addr, tx) \
    asm volatile("mbarrier.arrive.expect_tx.shared.b64 _, [%0], %1;" :: "r"(addr), "r"(tx) : "memory")
#define MBAR_WAIT(addr, ph) do {                                                  \
    asm volatile("{ .reg .pred P; WL%=:"                                          \
        " mbarrier.try_wait.parity.acquire.cta.shared::cta.b64 P, [%0], %1, 0x989680;" \
        " @P bra.uni WD%=; bra.uni WL%=; WD%=: }"                                 \
        :: "r"(addr), "r"(ph) : "memory");                                        \
} while (0)

DI void ldsm4(uint32_t* r, uint32_t addr) {
    asm volatile("ldmatrix.sync.aligned.m8n8.x4.shared.b16 {%0,%1,%2,%3}, [%4];"
                 : "=r"(r[0]), "=r"(r[1]), "=r"(r[2]), "=r"(r[3]) : "r"(addr));
}

DI void mma_f16(float* c, const uint32_t* a, const uint32_t* b) {
    asm volatile(
        "mma.sync.aligned.m16n8k16.row.col.f32.f16.f16.f32 "
        "{%0,%1,%2,%3}, {%4,%5,%6,%7}, {%8,%9}, {%0,%1,%2,%3};"
        : "+f"(c[0]), "+f"(c[1]), "+f"(c[2]), "+f"(c[3])
        : "r"(a[0]), "r"(a[1]), "r"(a[2]), "r"(a[3]), "r"(b[0]), "r"(b[1]));
}

// -------- block reduce (sum) for 256-thread blocks --------
DI float block_sum256(float v) {
    __shared__ float red[8];
    #pragma unroll
    for (int o = 16; o; o >>= 1) v += __shfl_xor_sync(0xFFFFFFFFu, v, o);
    if ((threadIdx.x & 31) == 0) red[threadIdx.x >> 5] = v;
    __syncthreads();
    if (threadIdx.x < 8) {
        v = red[threadIdx.x];
        #pragma unroll
        for (int o = 4; o; o >>= 1) v += __shfl_xor_sync(0xFFu, v, o);
        if (threadIdx.x == 0) red[0] = v;
    }
    __syncthreads();
    return red[0];
}

// ============ Kernel 1: L2-normalize rows -> fp16, repacked swizzled images ============
// 2 rows per 256-thread block; each thread covers 8 consecutive k (one 16B
// swizzle unit) -> single aligned 16B store.
__global__ void __launch_bounds__(256) norm_split_kernel(
    const float* __restrict__ p, const float* __restrict__ e, const float* __restrict__ c)
{
    int h = threadIdx.x >> 7;                 // which row of the pair
    int t = threadIdx.x & 127;                // thread within row
    int row = blockIdx.x * 2 + h;

    const float* src;
    char* arr;
    int prow;
    bool is_a = (row < B_ROWS);
    if (is_a) {
        src = p + (size_t)row * DIM;
        arr = (char*)g_a; prow = row;
    } else if (row < 2 * B_ROWS) {
        src = e + (size_t)(row - B_ROWS) * DIM;
        arr = (char*)g_b; prow = row - B_ROWS;
    } else {
        src = c + (size_t)(row - 2 * B_ROWS) * DIM;
        arr = (char*)g_b; prow = row - B_ROWS;   // contra after entail
    }
    int tile = prow >> 7, r = prow & 127;

    const float4* s4 = reinterpret_cast<const float4*>(src);
    float4 x0 = s4[t * 2 + 0];
    float4 x1 = s4[t * 2 + 1];
    float ss = (x0.x * x0.x + x0.y * x0.y + x0.z * x0.z + x0.w * x0.w)
             + (x1.x * x1.x + x1.y * x1.y + x1.z * x1.z + x1.w * x1.w);

    // per-row reduce: 4 warps per row
    __shared__ float red[8];
    #pragma unroll
    for (int o = 16; o; o >>= 1) ss += __shfl_xor_sync(0xFFFFFFFFu, ss, o);
    int w = threadIdx.x >> 5;
    if ((threadIdx.x & 31) == 0) red[w] = ss;
    __syncthreads();
    float tot = (red[h * 4 + 0] + red[h * 4 + 1]) + (red[h * 4 + 2] + red[h * 4 + 3]);
    float scale = (is_a ? 20.0f : 1.0f) / fmaxf(sqrtf(tot), 1e-8f);

    __half2 h0 = __floats2half2_rn(x0.x * scale, x0.y * scale);
    __half2 h1 = __floats2half2_rn(x0.z * scale, x0.w * scale);
    __half2 h2 = __floats2half2_rn(x1.x * scale, x1.y * scale);
    __half2 h3 = __floats2half2_rn(x1.z * scale, x1.w * scale);

    // k = t*8 .. t*8+7 -> chunk = t>>3, unit kc = t&7; one aligned 16B store
    int chunk = t >> 3;
    int kc = t & 7;
    char* dst = arr + (size_t)tile * TILE_STRIDE + (size_t)chunk * TCH_BYTES
                    + swz((uint32_t)(r * 128 + kc * 16));
    uint4 u;
    u.x = h2u(h0);
    u.y = h2u(h1);
    u.z = h2u(h2);
    u.w = h2u(h3);
    *reinterpret_cast<uint4*>(dst) = u;
}

// ============ Kernel 2: fp16 HMMA GEMM (bulk loader) + fused partial LSE ============
// 256 threads, CTA tile 128x128, warp tile 64x32, warps 2(M)x4(N),
// 3-stage cp.async.bulk pipeline with tx mbarriers; block-wide syncthreads
// protects slot recycling (WAR); ISSUE happens before the full-wait. 2 CTAs/SM.
__global__ void __launch_bounds__(256, 2) gemm_kernel(float* __restrict__ out) {
    extern __shared__ char smem[];
    __shared__ uint64_t mbars[NSTAGE];
    uint32_t sb = smem_u32(smem);
    uint32_t mb0 = smem_u32(mbars);
    int tid = threadIdx.x, w = tid >> 5, lane = tid & 31;

    // supertile swizzle: groups of 8 M-tiles, sweep all 128 N-tiles per group
    int sid = blockIdx.x;
    int group  = sid >> 10;
    int within = sid & 1023;
    int mt = (group << 3) + (within & 7);
    int nt = within >> 3;
    int m0 = mt * MT, n0 = nt * NT;

    const char* a_src = (const char*)g_a + (size_t)mt * TILE_STRIDE;
    const char* b_src = (const char*)g_b + (size_t)nt * TILE_STRIDE;

    int wm = w & 1, wn = w >> 1;
    int warp_m = wm * 64, warp_n = wn * 32;

    float acc[4][4][4];
    #pragma unroll
    for (int a = 0; a < 4; a++)
        #pragma unroll
        for (int b = 0; b < 4; b++)
            #pragma unroll
            for (int k = 0; k < 4; k++) acc[a][b][k] = 0.0f;

    if (tid == 0) {
        #pragma unroll
        for (int s = 0; s < NSTAGE; s++) MBAR_INIT(mb0 + 8 * s, 1);
    }
    __syncthreads();

    #define ISSUE(chunk_) do {                                                   \
        int s_ = (chunk_) % NSTAGE;                                               \
        uint32_t bar_ = mb0 + 8 * s_;                                             \
        uint32_t stage_ = sb + s_ * STAGE_BYTES;                                  \
        MBAR_EXPECT_TX(bar_, STAGE_BYTES);                                        \
        bulk_g2s(stage_,              a_src + (size_t)(chunk_) * TCH_BYTES, TCH_BYTES, bar_); \
        bulk_g2s(stage_ + TILE_BYTES, b_src + (size_t)(chunk_) * TCH_BYTES, TCH_BYTES, bar_); \
    } while (0)

    if (tid == 0) { ISSUE(0); ISSUE(1); }

    int arow = warp_m + (lane & 15);
    int acol = (lane >> 4);
    int brow = (lane & 7) + ((lane >> 4) << 3);
    int bkh  = (lane >> 3) & 1;

    for (int chunk = 0; chunk < NCHUNK; ++chunk) {
        int slot = chunk % NSTAGE;
        int ph = (chunk / NSTAGE) & 1;
        __syncthreads();                      // all warps done with chunk-1 (incl. its slot reads)
        if (chunk + 2 < NCHUNK && tid == 0) ISSUE(chunk + 2);   // recycle chunk-1's slot (safe)
        MBAR_WAIT(mb0 + 8 * slot, ph);        // RAW: this chunk's data ready

        uint32_t stage = sb + slot * STAGE_BYTES;
        uint32_t A = stage, Bt = stage + TILE_BYTES;

        #pragma unroll
        for (int kk = 0; kk < 4; kk++) {
            uint32_t a_r[4][4];
            #pragma unroll
            for (int mb = 0; mb < 4; mb++) {
                uint32_t off = swz((uint32_t)(arow + mb * 16) * 128 + kk * 32 + acol * 16);
                ldsm4(a_r[mb], A + off);
            }
            uint32_t b_r[2][4];
            #pragma unroll
            for (int p = 0; p < 2; p++) {
                uint32_t off = swz((uint32_t)(warp_n + p * 16 + brow) * 128 + kk * 32 + bkh * 16);
                ldsm4(b_r[p], Bt + off);
            }
            #pragma unroll
            for (int mb = 0; mb < 4; mb++)
                #pragma unroll
                for (int p = 0; p < 2; p++)
                    #pragma unroll
                    for (int sub = 0; sub < 2; sub++)
                        mma_f16(acc[mb][p * 2 + sub], a_r[mb], &b_r[p][sub * 2]);
        }
    }

    // ---- epilogue 1: store sims (streaming scalar stores; base is 4B-aligned) ----
    float* o = out + 1;
    #pragma unroll
    for (int mb = 0; mb < 4; mb++) {
        int row = m0 + warp_m + mb * 16 + (lane >> 2);
        #pragma unroll
        for (int nb = 0; nb < 4; nb++) {
            int col = n0 + warp_n + nb * 8 + (lane & 3) * 2;
            float* p0 = o + (size_t)row * NCOLS + col;
            __stcs(p0 + 0, acc[mb][nb][0]);
            __stcs(p0 + 1, acc[mb][nb][1]);
            float* p1 = p0 + (size_t)8 * NCOLS;
            __stcs(p1 + 0, acc[mb][nb][2]);
            __stcs(p1 + 1, acc[mb][nb][3]);
        }
    }

    // ---- epilogue 2: fused partial logsumexp (sum of exp(sim - 20)) ----
    auto exp_poly = [](float v) -> float {       // e^v for v in [-45, ~1e-2]
        float t = v * 1.4426950408889634f;
        float fi = floorf(t);
        float f = t - fi;
        float p = 1.5403530393283441e-4f;
        p = p * f + 1.3333558146428443e-3f;
        p = p * f + 9.6181291076284771e-3f;
        p = p * f + 5.5504108664821580e-2f;
        p = p * f + 2.4022650695910071e-1f;
        p = p * f + 6.9314718055994531e-1f;
        p = p * f + 1.0f;
        return __int_as_float(((int)fi + 127) << 23) * p;
    };

    float s[8];
    #pragma unroll
    for (int i = 0; i < 8; i++) s[i] = 0.0f;
    #pragma unroll
    for (int mb = 0; mb < 4; mb++)
        #pragma unroll
        for (int nb = 0; nb < 4; nb++) {
            s[mb * 2 + 0] += exp_poly(acc[mb][nb][0] - 20.0f) + exp_poly(acc[mb][nb][1] - 20.0f);
            s[mb * 2 + 1] += exp_poly(acc[mb][nb][2] - 20.0f) + exp_poly(acc[mb][nb][3] - 20.0f);
        }
    #pragma unroll
    for (int i = 0; i < 8; i++) {
        s[i] += __shfl_xor_sync(0xFFFFFFFFu, s[i], 1);
        s[i] += __shfl_xor_sync(0xFFFFFFFFu, s[i], 2);
    }
    float* sred = reinterpret_cast<float*>(smem);   // [4 wn][128 rows]
    __syncthreads();     // all warps done with final chunk's slot reads
    if ((lane & 3) == 0) {
        #pragma unroll
        for (int mb = 0; mb < 4; mb++) {
            int rl = warp_m + mb * 16 + (lane >> 2);
            sred[wn * 128 + rl]     = s[mb * 2 + 0];
            sred[wn * 128 + rl + 8] = s[mb * 2 + 1];
        }
    }
    __syncthreads();
    if (tid < 128) {
        float t = (sred[tid] + sred[128 + tid]) + (sred[256 + tid] + sred[384 + tid]);
        g_part[(size_t)(m0 + tid) * NTILE + nt] = t;
    }
    #undef ISSUE
}

// ============ Kernel 3: row loss from partials + fused final mean ============
__global__ void __launch_bounds__(256) lse_kernel(const float* __restrict__ sims,
                                                  float* __restrict__ out) {
    int w = threadIdx.x >> 5, lane = threadIdx.x & 31;
    int row = blockIdx.x * 8 + w;
    const float* pr = g_part + (size_t)row * NTILE;
    float s = (pr[lane] + pr[lane + 32]) + (pr[lane + 64] + pr[lane + 96]);
    #pragma unroll
    for (int o = 16; o; o >>= 1) s += __shfl_xor_sync(0xFFFFFFFFu, s, o);
    if (lane == 0) {
        float diag = sims[(size_t)row * NCOLS + row];
        g_rowloss[row] = 20.0f + logf(s) - diag;
    }

    // last-block-done: final mean (one block, fixed order -> deterministic)
    __shared__ int is_last;
    __threadfence();
    __syncthreads();
    if (threadIdx.x == 0) {
        int prev = atomicAdd(&g_done, 1);
        is_last = (prev == gridDim.x - 1);
    }
    __syncthreads();
    if (is_last) {
        __threadfence();
        float acc = 0.0f;
        for (int i = threadIdx.x; i < B_ROWS; i += 256) acc += g_rowloss[i];
        float tot = block_sum256(acc);
        if (threadIdx.x == 0) {
            out[0] = tot * (1.0f / (float)B_ROWS);
            g_done = 0;                         // self-reset for graph replays
        }
    }
}

// ============ launch ============
extern "C" void kernel_launch(void* const* d_in, const int* in_sizes, int n_in,
                              void* d_out, int out_size) {
    (void)in_sizes; (void)n_in; (void)out_size;
    const float* p = (const float*)d_in[0];
    const float* e = (const float*)d_in[1];
    const float* c = (const float*)d_in[2];
    float* out = (float*)d_out;

    norm_split_kernel<<<3 * B_ROWS / 2, 256>>>(p, e, c);

    cudaFuncSetAttribute(gemm_kernel, cudaFuncAttributeMaxDynamicSharedMemorySize, SMEM_BYTES);
    gemm_kernel<<<(B_ROWS / MT) * (NCOLS / NT), 256, SMEM_BYTES>>>(out);

    lse_kernel<<<B_ROWS / 8, 256>>>(out + 1, out);
}